// round 2
// baseline (speedup 1.0000x reference)
#include <cuda_runtime.h>
#include <cstdint>

// Instant-NGP hash grid: D=3, L=16, C=2, H=16, MAX_PARAMS=2^19
// Levels 0..2 dense ((res+1)^3 entries), levels 3..15 hashed (2^19 entries).
#define NB 524288u          // points
#define HASH_MASK 0x7FFFFu  // 2^19 - 1

__constant__ unsigned c_level_off[16] = {
    0u,       4913u,    40850u,   315475u,
    839763u,  1364051u, 1888339u, 2412627u,
    2936915u, 3461203u, 3985491u, 4509779u,
    5034067u, 5558355u, 6082643u, 6606931u
};

struct LevelData {
    unsigned idx[8];
    float w[8];
    const float2* table;
};

__device__ __forceinline__ void prep_level(unsigned l,
                                           float px, float py, float pz,
                                           const float2* __restrict__ embt,
                                           LevelData& L)
{
    unsigned res = 16u << l;
    float fres = (float)res;
    float posx = px * fres, posy = py * fres, posz = pz * fres;
    float gx = floorf(posx), gy = floorf(posy), gz = floorf(posz);
    float fx = posx - gx, fy = posy - gy, fz = posz - gz;
    unsigned ix = (unsigned)gx, iy = (unsigned)gy, iz = (unsigned)gz;

    if (l < 3u) {
        // dense level: strided index [1, res+1, (res+1)^2]; coords <= res so in range
        unsigned r1 = res + 1u;
        unsigned s2 = r1 * r1;
        unsigned base = ix + iy * r1 + iz * s2;
        L.idx[0] = base;
        L.idx[1] = base + 1u;
        L.idx[2] = base + r1;
        L.idx[3] = base + r1 + 1u;
        L.idx[4] = base + s2;
        L.idx[5] = base + s2 + 1u;
        L.idx[6] = base + s2 + r1;
        L.idx[7] = base + s2 + r1 + 1u;
    } else {
        // hashed level: (x*1) ^ (y*p1) ^ (z*p2), masked to 2^19 entries
        unsigned hx0 = ix,               hx1 = ix + 1u;
        unsigned hy0 = iy * 2654435761u, hy1 = (iy + 1u) * 2654435761u;
        unsigned hz0 = iz * 805459861u,  hz1 = (iz + 1u) * 805459861u;
        L.idx[0] = (hx0 ^ hy0 ^ hz0) & HASH_MASK;
        L.idx[1] = (hx1 ^ hy0 ^ hz0) & HASH_MASK;
        L.idx[2] = (hx0 ^ hy1 ^ hz0) & HASH_MASK;
        L.idx[3] = (hx1 ^ hy1 ^ hz0) & HASH_MASK;
        L.idx[4] = (hx0 ^ hy0 ^ hz1) & HASH_MASK;
        L.idx[5] = (hx1 ^ hy0 ^ hz1) & HASH_MASK;
        L.idx[6] = (hx0 ^ hy1 ^ hz1) & HASH_MASK;
        L.idx[7] = (hx1 ^ hy1 ^ hz1) & HASH_MASK;
    }

    float gx0 = 1.0f - fx, gy0 = 1.0f - fy, gz0 = 1.0f - fz;
    L.w[0] = gx0 * gy0 * gz0;
    L.w[1] = fx  * gy0 * gz0;
    L.w[2] = gx0 * fy  * gz0;
    L.w[3] = fx  * fy  * gz0;
    L.w[4] = gx0 * gy0 * fz;
    L.w[5] = fx  * gy0 * fz;
    L.w[6] = gx0 * fy  * fz;
    L.w[7] = fx  * fy  * fz;

    L.table = embt + c_level_off[l];
}

__global__ __launch_bounds__(256)
void hash_encode_kernel(const float* __restrict__ xin,
                        const float* __restrict__ emb,
                        float* __restrict__ out)
{
    unsigned tid = blockIdx.x * blockDim.x + threadIdx.x;  // exact grid
    unsigned b = tid >> 3;      // point
    unsigned k = tid & 7u;      // level pair
    unsigned l0 = k << 1;       // levels l0, l0+1

    // map [-1,1] -> [0,1] (matches reference: (x+1)/2)
    float px = (__ldg(xin + 3u * b + 0u) + 1.0f) * 0.5f;
    float py = (__ldg(xin + 3u * b + 1u) + 1.0f) * 0.5f;
    float pz = (__ldg(xin + 3u * b + 2u) + 1.0f) * 0.5f;

    const float2* embt = reinterpret_cast<const float2*>(emb);

    LevelData A, B;
    prep_level(l0,      px, py, pz, embt, A);
    prep_level(l0 + 1u, px, py, pz, embt, B);

    // Issue all 16 gathers back-to-back: MLP=16 per thread
    float2 a0 = __ldg(A.table + A.idx[0]);
    float2 a1 = __ldg(A.table + A.idx[1]);
    float2 a2 = __ldg(A.table + A.idx[2]);
    float2 a3 = __ldg(A.table + A.idx[3]);
    float2 a4 = __ldg(A.table + A.idx[4]);
    float2 a5 = __ldg(A.table + A.idx[5]);
    float2 a6 = __ldg(A.table + A.idx[6]);
    float2 a7 = __ldg(A.table + A.idx[7]);
    float2 b0 = __ldg(B.table + B.idx[0]);
    float2 b1 = __ldg(B.table + B.idx[1]);
    float2 b2 = __ldg(B.table + B.idx[2]);
    float2 b3 = __ldg(B.table + B.idx[3]);
    float2 b4 = __ldg(B.table + B.idx[4]);
    float2 b5 = __ldg(B.table + B.idx[5]);
    float2 b6 = __ldg(B.table + B.idx[6]);
    float2 b7 = __ldg(B.table + B.idx[7]);

    float ox0 = A.w[0]*a0.x + A.w[1]*a1.x + A.w[2]*a2.x + A.w[3]*a3.x
              + A.w[4]*a4.x + A.w[5]*a5.x + A.w[6]*a6.x + A.w[7]*a7.x;
    float oy0 = A.w[0]*a0.y + A.w[1]*a1.y + A.w[2]*a2.y + A.w[3]*a3.y
              + A.w[4]*a4.y + A.w[5]*a5.y + A.w[6]*a6.y + A.w[7]*a7.y;
    float ox1 = B.w[0]*b0.x + B.w[1]*b1.x + B.w[2]*b2.x + B.w[3]*b3.x
              + B.w[4]*b4.x + B.w[5]*b5.x + B.w[6]*b6.x + B.w[7]*b7.x;
    float oy1 = B.w[0]*b0.y + B.w[1]*b1.y + B.w[2]*b2.y + B.w[3]*b3.y
              + B.w[4]*b4.y + B.w[5]*b5.y + B.w[6]*b6.y + B.w[7]*b7.y;

    // out[b, 32]: levels 2k,2k+1 -> floats b*32+4k .. b*32+4k+3, 16B aligned
    float4 r; r.x = ox0; r.y = oy0; r.z = ox1; r.w = oy1;
    reinterpret_cast<float4*>(out)[b * 8u + k] = r;
}

extern "C" void kernel_launch(void* const* d_in, const int* in_sizes, int n_in,
                              void* d_out, int out_size)
{
    const float* xin = (const float*)d_in[0];   // inputs  [B, 3]
    const float* emb = (const float*)d_in[1];   // embeddings [7131219, 2]
    float* out = (float*)d_out;                 // [B, 32] float

    unsigned total = NB * 8u;                   // 4194304 threads
    hash_encode_kernel<<<total / 256u, 256u>>>(xin, emb, out);
}